// round 2
// baseline (speedup 1.0000x reference)
#include <cuda_runtime.h>
#include <cuda_bf16.h>

// Problem constants
#define T_TOK 4096
#define H_DIM 1024
#define I_DIM 512
#define N_EXP 16

// Tiling
#define BM 128
#define BN 128
#define BK 32
#define SA_STRIDE 36   // 32 + 4 pad (conflict-free fragment reads)
#define SB_STRIDE 132  // 128 + 4 pad
#define NTHREADS 256
#define MT_MAX 48      // >= sum ceil(cnt_e/128) worst case = 32 + 16

// 16 MB scratch for gate_up output [T, 2I]
__device__ float g_gu[T_TOK * (2 * I_DIM)];

__device__ __forceinline__ unsigned f2tf32(float x) {
    unsigned r;
    asm("cvt.rna.tf32.f32 %0, %1;" : "=r"(r) : "f"(x));
    return r;
}

__device__ __forceinline__ void mma_tf32(float& d0, float& d1, float& d2, float& d3,
                                         unsigned a0, unsigned a1, unsigned a2, unsigned a3,
                                         unsigned b0, unsigned b1) {
    asm volatile(
        "mma.sync.aligned.m16n8k8.row.col.f32.tf32.tf32.f32 "
        "{%0,%1,%2,%3}, {%4,%5,%6,%7}, {%8,%9}, {%0,%1,%2,%3};\n"
        : "+f"(d0), "+f"(d1), "+f"(d2), "+f"(d3)
        : "r"(a0), "r"(a1), "r"(a2), "r"(a3), "r"(b0), "r"(b1));
}

// Grouped GEMM: C[m, 0:1024] = A'[m, 0:KDIM] @ Bw[expert(m)][KDIM, 1024]
//   FUSE=false: A' = A (x),            C = g_gu     (gate_up GEMM, KDIM=1024)
//   FUSE=true : A' = silu(g)*u from g_gu, C = C_out (down GEMM,    KDIM=512)
template <int KDIM, bool FUSE>
__global__ __launch_bounds__(NTHREADS, 2)
void grouped_gemm(const float* __restrict__ A,
                  const float* __restrict__ Bw,
                  const int* __restrict__ counts,
                  float* __restrict__ C) {
    // ---- map m-tile index -> (expert, row range) ----
    const int tile = blockIdx.x;
    int e = -1, m0 = 0, mEnd = 0;
    {
        int acc = 0, off = 0;
#pragma unroll
        for (int i = 0; i < N_EXP; i++) {
            int c = __ldg(counts + i);
            int nt = (c + BM - 1) >> 7;
            if (e < 0 && tile < acc + nt) {
                e = i;
                m0 = off + (tile - acc) * BM;
                mEnd = off + c;
            }
            acc += nt;
            off += c;
        }
    }
    if (e < 0) return;  // surplus block

    const int n0 = blockIdx.y * BN;
    const float* Ap = FUSE ? (const float*)g_gu : A;
    float* Cp = FUSE ? C : (float*)g_gu;
    const float* Bp = Bw + (size_t)e * KDIM * 1024;

    __shared__ unsigned sA[BM * SA_STRIDE];  // [m][k] tf32, stride 36
    __shared__ unsigned sB[BK * SB_STRIDE];  // [k][n] tf32, stride 132

    const int tid = threadIdx.x;
    const int lane = tid & 31;
    const int w = tid >> 5;        // 0..7
    const int wm = w & 1;          // 2 warp-rows  (64 rows each)
    const int wn = w >> 1;         // 4 warp-cols  (32 cols each)
    const int g = lane >> 2;       // groupID 0..7
    const int tg = lane & 3;       // thread-in-group 0..3

    // loader coords
    const int a_row = tid >> 3, a_quad = tid & 7;    // A: 32 rows x 8 quads per pass, 4 passes
    const int b_krow = tid >> 5, b_quad = tid & 31;  // B: 8 k-rows x 32 quads per pass, 4 passes

    float4 pa[4];  // A prefetch (post-SwiGLU if FUSE)
    float4 pb[4];  // B prefetch

    auto loadA = [&](int kt) {
#pragma unroll
        for (int p = 0; p < 4; p++) {
            int gm = m0 + a_row + p * 32;
            int col = kt * BK + a_quad * 4;
            float4 v = make_float4(0.f, 0.f, 0.f, 0.f);
            if (gm < mEnd) {
                if (!FUSE) {
                    v = *(const float4*)(Ap + (size_t)gm * 1024 + col);
                } else {
                    float4 gg = *(const float4*)(Ap + (size_t)gm * 1024 + col);
                    float4 uu = *(const float4*)(Ap + (size_t)gm * 1024 + col + I_DIM);
                    v.x = gg.x / (1.f + __expf(-gg.x)) * uu.x;
                    v.y = gg.y / (1.f + __expf(-gg.y)) * uu.y;
                    v.z = gg.z / (1.f + __expf(-gg.z)) * uu.z;
                    v.w = gg.w / (1.f + __expf(-gg.w)) * uu.w;
                }
            }
            pa[p] = v;
        }
    };
    auto loadB = [&](int kt) {
#pragma unroll
        for (int p = 0; p < 4; p++) {
            int k = b_krow + p * 8;
            pb[p] = *(const float4*)(Bp + (size_t)(kt * BK + k) * 1024 + n0 + b_quad * 4);
        }
    };
    auto stsAB = [&]() {
#pragma unroll
        for (int p = 0; p < 4; p++) {
            int r = (a_row + p * 32) * SA_STRIDE + a_quad * 4;
            sA[r + 0] = f2tf32(pa[p].x);
            sA[r + 1] = f2tf32(pa[p].y);
            sA[r + 2] = f2tf32(pa[p].z);
            sA[r + 3] = f2tf32(pa[p].w);
        }
#pragma unroll
        for (int p = 0; p < 4; p++) {
            int r = (b_krow + p * 8) * SB_STRIDE + b_quad * 4;
            sB[r + 0] = f2tf32(pb[p].x);
            sB[r + 1] = f2tf32(pb[p].y);
            sB[r + 2] = f2tf32(pb[p].z);
            sB[r + 3] = f2tf32(pb[p].w);
        }
    };

    float acc[4][4][4];
#pragma unroll
    for (int i = 0; i < 4; i++)
#pragma unroll
        for (int j = 0; j < 4; j++)
#pragma unroll
            for (int q = 0; q < 4; q++) acc[i][j][q] = 0.f;

    const int KT = KDIM / BK;
    loadA(0);
    loadB(0);

    for (int t = 0; t < KT; t++) {
        stsAB();
        __syncthreads();
        if (t + 1 < KT) {  // issue next tile's global loads before compute (latency overlap)
            loadA(t + 1);
            loadB(t + 1);
        }
#pragma unroll
        for (int kk = 0; kk < BK; kk += 8) {
            unsigned af[4][4];
            unsigned bf[4][2];
#pragma unroll
            for (int mf = 0; mf < 4; mf++) {
                int rb = (wm * 64 + mf * 16 + g) * SA_STRIDE;
                af[mf][0] = sA[rb + kk + tg];
                af[mf][1] = sA[rb + 8 * SA_STRIDE + kk + tg];
                af[mf][2] = sA[rb + kk + tg + 4];
                af[mf][3] = sA[rb + 8 * SA_STRIDE + kk + tg + 4];
            }
#pragma unroll
            for (int nf = 0; nf < 4; nf++) {
                int nb = wn * 32 + nf * 8 + g;
                bf[nf][0] = sB[(kk + tg) * SB_STRIDE + nb];
                bf[nf][1] = sB[(kk + tg + 4) * SB_STRIDE + nb];
            }
#pragma unroll
            for (int mf = 0; mf < 4; mf++)
#pragma unroll
                for (int nf = 0; nf < 4; nf++)
                    mma_tf32(acc[mf][nf][0], acc[mf][nf][1], acc[mf][nf][2], acc[mf][nf][3],
                             af[mf][0], af[mf][1], af[mf][2], af[mf][3],
                             bf[nf][0], bf[nf][1]);
        }
        __syncthreads();
    }

    // ---- epilogue: fp32 stores, masked at segment end ----
#pragma unroll
    for (int mf = 0; mf < 4; mf++) {
#pragma unroll
        for (int nf = 0; nf < 4; nf++) {
            int r0 = m0 + wm * 64 + mf * 16 + g;
            int cc = n0 + wn * 32 + nf * 8 + 2 * tg;
            if (r0 < mEnd) {
                float2 v = make_float2(acc[mf][nf][0], acc[mf][nf][1]);
                *(float2*)(Cp + (size_t)r0 * 1024 + cc) = v;
            }
            if (r0 + 8 < mEnd) {
                float2 v = make_float2(acc[mf][nf][2], acc[mf][nf][3]);
                *(float2*)(Cp + (size_t)(r0 + 8) * 1024 + cc) = v;
            }
        }
    }
}

extern "C" void kernel_launch(void* const* d_in, const int* in_sizes, int n_in,
                              void* d_out, int out_size) {
    const float* x    = (const float*)d_in[0];  // [T, H]
    const float* gup  = (const float*)d_in[1];  // [E, H, 2I]
    const float* down = (const float*)d_in[2];  // [E, I, H]
    const int* counts = (const int*)d_in[3];    // [E]
    float* out = (float*)d_out;                 // [T, H]

    dim3 grid(MT_MAX, 8);
    dim3 block(NTHREADS);
    grouped_gemm<1024, false><<<grid, block>>>(x, gup, counts, nullptr);
    grouped_gemm<512, true><<<grid, block>>>(nullptr, down, counts, out);
}

// round 6
// speedup vs baseline: 1.1478x; 1.1478x over previous
#include <cuda_runtime.h>
#include <cstdint>

#define N_EXP 16
#define MT_MAX 48
#define NTH 256
#define SA_ROWF 264                       // floats per A smem row (132 float2)
#define SA_FLOATS (16 * SA_ROWF)          // 4224
#define SB_ROWF 136                       // floats per B smem row (128 + 8 pad)
#define SB_FLOATS (32 * SB_ROWF)          // 4352
#define STG_FLOATS (SA_FLOATS + SB_FLOATS)
#define SMEM_BYTES (2 * STG_FLOATS * 4)   // 68608 B

// 8MB scratch: silu(g)*u activations [4096, 512]
__device__ float g_act[4096 * 512];

// rna-to-tf32: bump magnitude past the truncation point (HW ignores low 13 bits)
__device__ __forceinline__ float frnd(float f) {
    return __uint_as_float(__float_as_uint(f) + 0x1000u);
}

__device__ __forceinline__ void mma_tf32(float& d0, float& d1, float& d2, float& d3,
                                         unsigned a0, unsigned a1, unsigned a2, unsigned a3,
                                         unsigned b0, unsigned b1) {
    asm volatile(
        "mma.sync.aligned.m16n8k8.row.col.f32.tf32.tf32.f32 "
        "{%0,%1,%2,%3}, {%4,%5,%6,%7}, {%8,%9}, {%0,%1,%2,%3};\n"
        : "+f"(d0), "+f"(d1), "+f"(d2), "+f"(d3)
        : "r"(a0), "r"(a1), "r"(a2), "r"(a3), "r"(b0), "r"(b1));
}

// PASS2=0: gu GEMM. A=x[T,1024]; B cols interleaved (16 g / 16 u groups) so each
//          warp holds matching g,u accumulators; epilogue writes silu(g)*u -> g_act.
// PASS2=1: down GEMM. A=g_act[T,512]; B=down[e]; epilogue -> C.
template <int KDIM, int PASS2>
__global__ __launch_bounds__(NTH, 2)
void moe_gemm(const float* __restrict__ A, const float* __restrict__ Bw,
              const int* __restrict__ counts, float* __restrict__ C) {
    extern __shared__ float dsm[];
    const int tid = threadIdx.x;

    // ---- m-tile -> (expert, rows) ----
    int e = -1, m0 = 0, mEnd = 0;
    {
        int accT = 0, off = 0;
#pragma unroll
        for (int i = 0; i < N_EXP; i++) {
            int c = __ldg(counts + i);
            int nt = (c + 127) >> 7;
            if (e < 0 && (int)blockIdx.x < accT + nt) {
                e = i; m0 = off + (blockIdx.x - accT) * 128; mEnd = off + c;
            }
            accT += nt; off += c;
        }
    }
    if (e < 0) return;

    const int by = blockIdx.y;
    const int n0 = by * (PASS2 ? 128 : 64);
    const float* Ap = PASS2 ? (const float*)g_act : A;
    const float* Bp = Bw + (size_t)e * KDIM * 1024;
    const int LDA = PASS2 ? 512 : 1024;

    const int lane = tid & 31, w = tid >> 5;
    const int wm = w & 1, wn = w >> 1;        // warp tile: 64m x 32n
    const int g = lane >> 2, tg = lane & 3;
    const int a_mr = tid >> 3, a_j = tid & 7; // A producer: row, k-quad
    const int a_kk = a_j >> 1, a_q = a_j & 1;
    const int b_k = tid >> 3, b_c = tid & 7;  // B producer: k-row, chunk

    float4 pa[4];

    auto ldgA = [&](int t) {
#pragma unroll
        for (int p = 0; p < 4; p++) {
            int gm = m0 + a_mr + 32 * p;
            pa[p] = (gm < mEnd)
                ? *(const float4*)(Ap + (size_t)gm * LDA + t * 32 + a_j * 4)
                : make_float4(0.f, 0.f, 0.f, 0.f);
        }
    };
    auto stsA = [&](int s) {
        float* sA = dsm + s * STG_FLOATS;
#pragma unroll
        for (int p = 0; p < 4; p++) {
            int m = a_mr + 32 * p;
            int mx = ((m ^ (a_kk << 3)) << 1) + a_q;
            float v[4] = {pa[p].x, pa[p].y, pa[p].z, pa[p].w};
#pragma unroll
            for (int c = 0; c < 4; c++)
                sA[(a_kk * 4 + c) * SA_ROWF + mx] = frnd(v[c]);
        }
    };
    auto cpB = [&](int t, int s) {
        float* sB = dsm + s * STG_FLOATS + SA_FLOATS;
#pragma unroll
        for (int p = 0; p < 4; p++) {
            int nl = b_c + 8 * p;
            int iext;
            if (PASS2) iext = n0 + 4 * nl;
            else       iext = n0 + ((nl >> 3) << 4) + ((nl & 3) << 2) + (((nl >> 2) & 1) << 9);
            const float* src = Bp + (size_t)(t * 32 + b_k) * 1024 + iext;
            unsigned dst = (unsigned)__cvta_generic_to_shared(sB + b_k * SB_ROWF + 4 * nl);
            asm volatile("cp.async.cg.shared.global [%0], [%1], 16;" :: "r"(dst), "l"(src));
        }
    };

    float acc4[4][4][4];
#pragma unroll
    for (int i = 0; i < 4; i++)
#pragma unroll
        for (int j = 0; j < 4; j++)
#pragma unroll
            for (int q = 0; q < 4; q++) acc4[i][j][q] = 0.f;

    auto compute = [&](int s) {
        const float2* sA2 = (const float2*)(dsm + s * STG_FLOATS);
        const float* sB = dsm + s * STG_FLOATS + SA_FLOATS;
#pragma unroll
        for (int ks = 0; ks < 4; ks++) {
            unsigned af[4][4], bf[4][2];
#pragma unroll
            for (int mf = 0; mf < 4; mf++) {
                int ml = wm * 64 + mf * 16 + g;
                int rb = (ks * 4 + tg) * 132;
                float2 lo = sA2[rb + (ml ^ (ks << 3))];
                float2 hi = sA2[rb + ((ml + 8) ^ (ks << 3))];
                af[mf][0] = __float_as_uint(lo.x);
                af[mf][1] = __float_as_uint(hi.x);
                af[mf][2] = __float_as_uint(lo.y);
                af[mf][3] = __float_as_uint(hi.y);
            }
#pragma unroll
            for (int nf = 0; nf < 4; nf++) {
                int nb = wn * 32 + nf * 8 + g;
                bf[nf][0] = __float_as_uint(sB[(ks * 8 + tg) * SB_ROWF + nb]) + 0x1000u;
                bf[nf][1] = __float_as_uint(sB[(ks * 8 + tg + 4) * SB_ROWF + nb]) + 0x1000u;
            }
#pragma unroll
            for (int mf = 0; mf < 4; mf++)
#pragma unroll
                for (int nf = 0; nf < 4; nf++)
                    mma_tf32(acc4[mf][nf][0], acc4[mf][nf][1], acc4[mf][nf][2], acc4[mf][nf][3],
                             af[mf][0], af[mf][1], af[mf][2], af[mf][3],
                             bf[nf][0], bf[nf][1]);
        }
    };

    // ---- pipelined mainloop (2 stages, 1 sync per ktile) ----
    const int KT = KDIM / 32;
    ldgA(0);
    cpB(0, 0);
    asm volatile("cp.async.commit_group;");
    stsA(0);
    asm volatile("cp.async.wait_group 0;" ::: "memory");
    __syncthreads();

    for (int t = 0; t < KT; t++) {
        int cur = t & 1, nxt = cur ^ 1;
        if (t + 1 < KT) {
            ldgA(t + 1);
            cpB(t + 1, nxt);
            asm volatile("cp.async.commit_group;");
        }
        compute(cur);
        if (t + 1 < KT) {
            stsA(nxt);
            asm volatile("cp.async.wait_group 0;" ::: "memory");
        }
        __syncthreads();
    }

    // ---- epilogue ----
    if (!PASS2) {
        // acc cols: nf 0..1 = g group, nf 2..3 = matching u group (same ext col)
#pragma unroll
        for (int mf = 0; mf < 4; mf++) {
#pragma unroll
            for (int nf = 0; nf < 2; nf++) {
                int row = m0 + wm * 64 + mf * 16 + g;
                int col = by * 64 + wn * 16 + nf * 8 + 2 * tg;
                if (row < mEnd) {
                    float g0 = acc4[mf][nf][0], g1 = acc4[mf][nf][1];
                    float u0 = acc4[mf][nf + 2][0], u1 = acc4[mf][nf + 2][1];
                    float2 v;
                    v.x = g0 / (1.f + __expf(-g0)) * u0;
                    v.y = g1 / (1.f + __expf(-g1)) * u1;
                    *(float2*)(g_act + (size_t)row * 512 + col) = v;
                }
                if (row + 8 < mEnd) {
                    float g0 = acc4[mf][nf][2], g1 = acc4[mf][nf][3];
                    float u0 = acc4[mf][nf + 2][2], u1 = acc4[mf][nf + 2][3];
                    float2 v;
                    v.x = g0 / (1.f + __expf(-g0)) * u0;
                    v.y = g1 / (1.f + __expf(-g1)) * u1;
                    *(float2*)(g_act + (size_t)(row + 8) * 512 + col) = v;
                }
            }
        }
    } else {
#pragma unroll
        for (int mf = 0; mf < 4; mf++) {
#pragma unroll
            for (int nf = 0; nf < 4; nf++) {
                int row = m0 + wm * 64 + mf * 16 + g;
                int col = n0 + wn * 32 + nf * 8 + 2 * tg;
                if (row < mEnd) {
                    float2 v = make_float2(acc4[mf][nf][0], acc4[mf][nf][1]);
                    *(float2*)(C + (size_t)row * 1024 + col) = v;
                }
                if (row + 8 < mEnd) {
                    float2 v = make_float2(acc4[mf][nf][2], acc4[mf][nf][3]);
                    *(float2*)(C + (size_t)(row + 8) * 1024 + col) = v;
                }
            }
        }
    }
}

extern "C" void kernel_launch(void* const* d_in, const int* in_sizes, int n_in,
                              void* d_out, int out_size) {
    const float* x    = (const float*)d_in[0];  // [4096, 1024]
    const float* gup  = (const float*)d_in[1];  // [16, 1024, 1024]
    const float* down = (const float*)d_in[2];  // [16, 512, 1024]
    const int* counts = (const int*)d_in[3];    // [16]
    float* out = (float*)d_out;                 // [4096, 1024]

    cudaFuncSetAttribute(moe_gemm<1024, 0>, cudaFuncAttributeMaxDynamicSharedMemorySize, SMEM_BYTES);
    cudaFuncSetAttribute(moe_gemm<512, 1>, cudaFuncAttributeMaxDynamicSharedMemorySize, SMEM_BYTES);

    moe_gemm<1024, 0><<<dim3(MT_MAX, 8), NTH, SMEM_BYTES>>>(x, gup, counts, nullptr);
    moe_gemm<512, 1><<<dim3(MT_MAX, 8), NTH, SMEM_BYTES>>>(nullptr, down, counts, out);
}